// round 9
// baseline (speedup 1.0000x reference)
#include <cuda_runtime.h>
#include <cstdint>

// Gumbel-Sinkhorn, B=16, N=256, TAU=0.1, 100 iterations.
//
// Primal Sinkhorn-Knopp on the constant matrix E = exp(a/tau - m):
//   e[i] = 1 / sum_j E[i][j] * d[j]     (row normalize)
//   d[j] = 1 / sum_i E[i][j] * e[i]     (col normalize)
//   out  = E[i][j] * e[i] * d[j]
// R8: 8-CTA cluster, TWO matrices per cluster interleaved so each matrix's
// DSMEM exchange latency is hidden behind the other matrix's compute.
// Exchange per matrix per iter: 7x 1KB cp.async.bulk to the peers (self slice
// staged locally, no self-copy), issued by 7 lanes in parallel; one mbarrier
// parity wait. E in registers in both layouts (2 matrices x 16 = 32 regs).

namespace {
constexpr int NMAT    = 16;
constexpr int N       = 256;
constexpr int CSZ     = 8;           // cluster size (CTAs per matrix pair)
constexpr int ROWS    = N / CSZ;     // 32 rows per CTA per matrix
constexpr int THREADS = 1024;
constexpr int NWARP   = THREADS / 32;
constexpr int NITER   = 100;
constexpr float INV_TAU = 10.0f;
constexpr unsigned SLICE_BYTES = N * 4;                    // 1024 B
constexpr unsigned TX_BYTES    = SLICE_BYTES * (CSZ - 1);  // 7168 B from peers
}

__device__ __forceinline__ uint32_t smem_u32(const void* p) {
    return (uint32_t)__cvta_generic_to_shared(p);
}

__device__ __forceinline__ uint32_t mapa_rank(uint32_t laddr, uint32_t rank) {
    uint32_t rem;
    asm volatile("mapa.shared::cluster.u32 %0, %1, %2;" : "=r"(rem) : "r"(laddr), "r"(rank));
    return rem;
}

// Plain remote store (prologue max-exchange only).
__device__ __forceinline__ void st_cluster_f32(uint32_t laddr, uint32_t rank, float v) {
    uint32_t rem = mapa_rank(laddr, rank);
    asm volatile("st.shared::cluster.f32 [%0], %1;" :: "r"(rem), "f"(v) : "memory");
}

// 1KB bulk copy: local SMEM -> remote cluster SMEM, completion as a single
// complete_tx at the destination CTA's mbarrier.
__device__ __forceinline__ void bulk_s2s(uint32_t dst_cluster, uint32_t src_local,
                                         uint32_t bytes, uint32_t mbar_cluster) {
    asm volatile(
        "cp.async.bulk.shared::cluster.shared::cta.mbarrier::complete_tx::bytes "
        "[%0], [%1], %2, [%3];"
        :: "r"(dst_cluster), "r"(src_local), "r"(bytes), "r"(mbar_cluster) : "memory");
}

__device__ __forceinline__ void mbar_expect_tx(uint32_t addr, uint32_t bytes) {
    asm volatile("mbarrier.arrive.expect_tx.shared.b64 _, [%0], %1;"
                 :: "r"(addr), "r"(bytes) : "memory");
}

__device__ __forceinline__ void mbar_wait(uint32_t addr, uint32_t phase) {
    asm volatile(
        "{\n\t"
        ".reg .pred P;\n\t"
        "WLOOP_%=:\n\t"
        "mbarrier.try_wait.parity.acquire.cluster.shared::cta.b64 P, [%0], %1, 0x989680;\n\t"
        "@P bra WDONE_%=;\n\t"
        "bra WLOOP_%=;\n\t"
        "WDONE_%=:\n\t"
        "}"
        :: "r"(addr), "r"(phase) : "memory");
}

__device__ __forceinline__ void cluster_sync_all() {
    asm volatile("barrier.cluster.arrive.aligned;" ::: "memory");
    asm volatile("barrier.cluster.wait.aligned;" ::: "memory");
}

__global__ void __launch_bounds__(THREADS, 1) __cluster_dims__(CSZ, 1, 1)
sinkhorn_kernel(const float* __restrict__ A, float* __restrict__ Out)
{
    __shared__ __align__(16) float dA[N], dB[N];
    __shared__ __align__(16) float eA[ROWS], eB[ROWS];
    // exchange buffers: [parity][source rank][col]; own slot staged locally,
    // peer slots filled by their bulk copies.
    __shared__ __align__(16) float xA[2][CSZ][N];
    __shared__ __align__(16) float xB[2][CSZ][N];
    __shared__ __align__(8) unsigned long long mbA[2], mbB[2];
    __shared__ float redA[NWARP], redB[NWARP];
    __shared__ float mbuf[2][CSZ];

    const int tid  = threadIdx.x;
    const int w    = tid >> 5;
    const int l    = tid & 31;
    const int rank = blockIdx.x & (CSZ - 1);
    const int cl   = blockIdx.x >> 3;          // cluster id: matrices 2cl, 2cl+1

    const float* AmA = A   + (size_t)(2 * cl)     * N * N;
    const float* AmB = A   + (size_t)(2 * cl + 1) * N * N;
    float*       OmA = Out + (size_t)(2 * cl)     * N * N;
    float*       OmB = Out + (size_t)(2 * cl + 1) * N * N;

    if (tid == 0) {
        #pragma unroll
        for (int q = 0; q < 2; q++) {
            asm volatile("mbarrier.init.shared.b64 [%0], 1;" :: "r"(smem_u32(&mbA[q])) : "memory");
            asm volatile("mbarrier.init.shared.b64 [%0], 1;" :: "r"(smem_u32(&mbB[q])) : "memory");
        }
        asm volatile("fence.mbarrier_init.release.cluster;" ::: "memory");
    }

    // ---- row layout: warp w owns global row rank*32+w; lane l cols [8l,8l+8)
    const int grow = rank * ROWS + w;
    const int c0   = l * 8;

    float erA[8], erB[8];
    {
        float4 a0 = *(const float4*)(AmA + grow * N + c0);
        float4 a1 = *(const float4*)(AmA + grow * N + c0 + 4);
        erA[0]=a0.x; erA[1]=a0.y; erA[2]=a0.z; erA[3]=a0.w;
        erA[4]=a1.x; erA[5]=a1.y; erA[6]=a1.z; erA[7]=a1.w;
        float4 b0 = *(const float4*)(AmB + grow * N + c0);
        float4 b1 = *(const float4*)(AmB + grow * N + c0 + 4);
        erB[0]=b0.x; erB[1]=b0.y; erB[2]=b0.z; erB[3]=b0.w;
        erB[4]=b1.x; erB[5]=b1.y; erB[6]=b1.z; erB[7]=b1.w;
        #pragma unroll
        for (int k = 0; k < 8; k++) { erA[k] *= INV_TAU; erB[k] *= INV_TAU; }
    }

    // ---- col layout: thread t = 4*j + g owns column j, local rows [8g,8g+8)
    const int jc = tid >> 2;
    const int g  = tid & 3;
    float ecA[8], ecB[8];
    #pragma unroll
    for (int k = 0; k < 8; k++) {
        int r = (rank * ROWS + g * 8 + k) * N + jc;
        ecA[k] = AmA[r] * INV_TAU;
        ecB[k] = AmB[r] * INV_TAU;
    }

    // ---- per-matrix max (stable E = exp(a/tau - m))
    {
        float ma = erA[0], mb = erB[0];
        #pragma unroll
        for (int k = 1; k < 8; k++) { ma = fmaxf(ma, erA[k]); mb = fmaxf(mb, erB[k]); }
        #pragma unroll
        for (int off = 16; off; off >>= 1) {
            ma = fmaxf(ma, __shfl_xor_sync(0xffffffffu, ma, off));
            mb = fmaxf(mb, __shfl_xor_sync(0xffffffffu, mb, off));
        }
        if (l == 0) { redA[w] = ma; redB[w] = mb; }
    }
    __syncthreads();
    if (w < 2) {
        float v = (w == 0) ? redA[l] : redB[l];
        #pragma unroll
        for (int off = 16; off; off >>= 1)
            v = fmaxf(v, __shfl_xor_sync(0xffffffffu, v, off));
        if (l == 0) {
            uint32_t slot = smem_u32(&mbuf[w][rank]);
            #pragma unroll
            for (int r = 0; r < CSZ; r++) st_cluster_f32(slot, r, v);
        }
    }
    cluster_sync_all();   // orders mbuf stores AND mbarrier inits cluster-wide
    float mA = mbuf[0][0], mB = mbuf[1][0];
    #pragma unroll
    for (int r = 1; r < CSZ; r++) { mA = fmaxf(mA, mbuf[0][r]); mB = fmaxf(mB, mbuf[1][r]); }

    #pragma unroll
    for (int k = 0; k < 8; k++) {
        erA[k] = __expf(erA[k] - mA);  erB[k] = __expf(erB[k] - mB);
        ecA[k] = __expf(ecA[k] - mA);  ecB[k] = __expf(ecB[k] - mB);
    }

    if (tid < N) { dA[tid] = 1.0f; dB[tid] = 1.0f; }
    __syncthreads();

    // ---- hoisted cluster addresses for the issuing warps
    const uint32_t xA_local = smem_u32(&xA[0][0][0]);
    const uint32_t xB_local = smem_u32(&xB[0][0][0]);
    const uint32_t mA_local = smem_u32(&mbA[0]);
    const uint32_t mB_local = smem_u32(&mbB[0]);
    // warp 0 lanes 0-6 send A; warp 31 lanes 0-6 send B
    uint32_t dst_x = 0, dst_m = 0;
    if (l < CSZ - 1) {
        uint32_t dst = (uint32_t)l + ((l >= rank) ? 1u : 0u);
        if (w == 0)      { dst_x = mapa_rank(xA_local, dst); dst_m = mapa_rank(mA_local, dst); }
        else if (w == 31){ dst_x = mapa_rank(xB_local, dst); dst_m = mapa_rank(mB_local, dst); }
    }
    const uint32_t my_off_base = (uint32_t)rank * SLICE_BYTES;

    #pragma unroll 1
    for (int it = 0; it < NITER; it++) {
        const uint32_t par = (uint32_t)(it & 1);
        const uint32_t ph  = (uint32_t)((it >> 1) & 1);
        const uint32_t src_off = par * (CSZ * SLICE_BYTES) + my_off_base;

        // ======== A: row pass ========
        {
            float4 d0 = *(const float4*)&dA[c0];
            float4 d1 = *(const float4*)&dA[c0 + 4];
            float s = erA[0]*d0.x + erA[1]*d0.y + erA[2]*d0.z + erA[3]*d0.w
                    + erA[4]*d1.x + erA[5]*d1.y + erA[6]*d1.z + erA[7]*d1.w;
            #pragma unroll
            for (int off = 16; off; off >>= 1)
                s += __shfl_xor_sync(0xffffffffu, s, off);
            if (l == 0) eA[w] = __fdividef(1.0f, fmaxf(s, 1e-30f));
        }
        __syncthreads();

        // ======== A: col pass + local staging ========
        {
            float4 e0 = *(const float4*)&eA[g * 8];
            float4 e1 = *(const float4*)&eA[g * 8 + 4];
            float p = ecA[0]*e0.x + ecA[1]*e0.y + ecA[2]*e0.z + ecA[3]*e0.w
                    + ecA[4]*e1.x + ecA[5]*e1.y + ecA[6]*e1.z + ecA[7]*e1.w;
            p += __shfl_xor_sync(0xffffffffu, p, 1);
            p += __shfl_xor_sync(0xffffffffu, p, 2);
            if (g == 0) xA[par][rank][jc] = p;
        }
        __syncthreads();

        // ======== A: send to 7 peers (warp 0, lanes parallel) ========
        if (w == 0) {
            asm volatile("fence.proxy.async.shared::cta;" ::: "memory");
            if (l == 7) mbar_expect_tx(mA_local + par * 8, TX_BYTES);
            if (l < CSZ - 1)
                bulk_s2s(dst_x + src_off, xA_local + src_off, SLICE_BYTES,
                         dst_m + par * 8);
        }

        // ======== B: row pass ========
        {
            float4 d0 = *(const float4*)&dB[c0];
            float4 d1 = *(const float4*)&dB[c0 + 4];
            float s = erB[0]*d0.x + erB[1]*d0.y + erB[2]*d0.z + erB[3]*d0.w
                    + erB[4]*d1.x + erB[5]*d1.y + erB[6]*d1.z + erB[7]*d1.w;
            #pragma unroll
            for (int off = 16; off; off >>= 1)
                s += __shfl_xor_sync(0xffffffffu, s, off);
            if (l == 0) eB[w] = __fdividef(1.0f, fmaxf(s, 1e-30f));
        }
        __syncthreads();

        // ======== B: col pass + local staging ========
        {
            float4 e0 = *(const float4*)&eB[g * 8];
            float4 e1 = *(const float4*)&eB[g * 8 + 4];
            float p = ecB[0]*e0.x + ecB[1]*e0.y + ecB[2]*e0.z + ecB[3]*e0.w
                    + ecB[4]*e1.x + ecB[5]*e1.y + ecB[6]*e1.z + ecB[7]*e1.w;
            p += __shfl_xor_sync(0xffffffffu, p, 1);
            p += __shfl_xor_sync(0xffffffffu, p, 2);
            if (g == 0) xB[par][rank][jc] = p;
        }
        __syncthreads();

        // ======== B: send to 7 peers (warp 31, lanes parallel) ========
        if (w == 31) {
            asm volatile("fence.proxy.async.shared::cta;" ::: "memory");
            if (l == 7) mbar_expect_tx(mB_local + par * 8, TX_BYTES);
            if (l < CSZ - 1)
                bulk_s2s(dst_x + src_off, xB_local + src_off, SLICE_BYTES,
                         dst_m + par * 8);
        }

        // ======== combine A then B (warps 0-7) ========
        if (tid < N) {
            mbar_wait(mA_local + par * 8, ph);
            float f = xA[par][0][tid];
            #pragma unroll
            for (int r = 1; r < CSZ; r++) f += xA[par][r][tid];
            dA[tid] = __fdividef(1.0f, fmaxf(f, 1e-30f));

            mbar_wait(mB_local + par * 8, ph);
            float h = xB[par][0][tid];
            #pragma unroll
            for (int r = 1; r < CSZ; r++) h += xB[par][r][tid];
            dB[tid] = __fdividef(1.0f, fmaxf(h, 1e-30f));
        }
        __syncthreads();
    }

    // ======== epilogue: P = E * e[i] * d[j] for both matrices ========
    {
        float ev = eA[w];
        float4 d0 = *(const float4*)&dA[c0];
        float4 d1 = *(const float4*)&dA[c0 + 4];
        float4 o;
        o.x = erA[0]*ev*d0.x; o.y = erA[1]*ev*d0.y;
        o.z = erA[2]*ev*d0.z; o.w = erA[3]*ev*d0.w;
        *(float4*)(OmA + grow * N + c0) = o;
        o.x = erA[4]*ev*d1.x; o.y = erA[5]*ev*d1.y;
        o.z = erA[6]*ev*d1.z; o.w = erA[7]*ev*d1.w;
        *(float4*)(OmA + grow * N + c0 + 4) = o;
    }
    {
        float ev = eB[w];
        float4 d0 = *(const float4*)&dB[c0];
        float4 d1 = *(const float4*)&dB[c0 + 4];
        float4 o;
        o.x = erB[0]*ev*d0.x; o.y = erB[1]*ev*d0.y;
        o.z = erB[2]*ev*d0.z; o.w = erB[3]*ev*d0.w;
        *(float4*)(OmB + grow * N + c0) = o;
        o.x = erB[4]*ev*d1.x; o.y = erB[5]*ev*d1.y;
        o.z = erB[6]*ev*d1.z; o.w = erB[7]*ev*d1.w;
        *(float4*)(OmB + grow * N + c0 + 4) = o;
    }

    // keep all CTAs alive until every in-flight bulk copy has been consumed
    cluster_sync_all();
}

extern "C" void kernel_launch(void* const* d_in, const int* in_sizes, int n_in,
                              void* d_out, int out_size) {
    const float* alpha = (const float*)d_in[0];
    float* out = (float*)d_out;
    sinkhorn_kernel<<<(NMAT / 2) * CSZ, THREADS>>>(alpha, out);
}

// round 10
// speedup vs baseline: 1.2244x; 1.2244x over previous
#include <cuda_runtime.h>
#include <cstdint>

// Gumbel-Sinkhorn, B=16, N=256, TAU=0.1, 100 iterations.
//
// Primal Sinkhorn-Knopp on the constant matrix E = exp(a/tau - m):
//   e[i] = 1 / sum_j E[i][j] * d[j]     (row normalize)
//   d[j] = 1 / sum_i E[i][j] * e[i]     (col normalize)
//   out  = E[i][j] * e[i] * d[j]
// R9: 4-CTA cluster, 64 rows/CTA, E in registers in ROW layout only.
// After the row butterfly every lane holds the row sums, so col-partial
// contributions are formed directly from er (no col-layout regs, no e_vec
// SMEM round-trip). Local col sums via a 32-deep SMEM workspace reduction.
// Exchange: 256 threads each push 1 float to 3 peers via st.shared::cluster,
// published by fence.acq_rel.cluster + 3 remote mbarrier arrives (count=3,
// double-buffered parity). No bulk engine, no cluster barrier in the loop.

namespace {
constexpr int NMAT    = 16;
constexpr int N       = 256;
constexpr int CSZ     = 4;           // cluster size (CTAs per matrix)
constexpr int ROWS    = N / CSZ;     // 64 rows per CTA
constexpr int THREADS = 1024;
constexpr int NWARP   = THREADS / 32;
constexpr int NITER   = 100;
constexpr float INV_TAU = 10.0f;
}

__device__ __forceinline__ uint32_t smem_u32(const void* p) {
    return (uint32_t)__cvta_generic_to_shared(p);
}

__device__ __forceinline__ uint32_t mapa_rank(uint32_t laddr, uint32_t rank) {
    uint32_t rem;
    asm volatile("mapa.shared::cluster.u32 %0, %1, %2;" : "=r"(rem) : "r"(laddr), "r"(rank));
    return rem;
}

__device__ __forceinline__ void st_cluster_f32_addr(uint32_t raddr, float v) {
    asm volatile("st.shared::cluster.f32 [%0], %1;" :: "r"(raddr), "f"(v) : "memory");
}

__device__ __forceinline__ void st_cluster_f32(uint32_t laddr, uint32_t rank, float v) {
    st_cluster_f32_addr(mapa_rank(laddr, rank), v);
}

__device__ __forceinline__ void mbar_arrive_cluster(uint32_t raddr) {
    asm volatile("mbarrier.arrive.shared::cluster.b64 _, [%0];" :: "r"(raddr) : "memory");
}

__device__ __forceinline__ void mbar_wait(uint32_t addr, uint32_t phase) {
    asm volatile(
        "{\n\t"
        ".reg .pred P;\n\t"
        "WLOOP_%=:\n\t"
        "mbarrier.try_wait.parity.acquire.cluster.shared::cta.b64 P, [%0], %1, 0x989680;\n\t"
        "@P bra WDONE_%=;\n\t"
        "bra WLOOP_%=;\n\t"
        "WDONE_%=:\n\t"
        "}"
        :: "r"(addr), "r"(phase) : "memory");
}

__device__ __forceinline__ void fence_cluster() {
    asm volatile("fence.acq_rel.cluster;" ::: "memory");
}

__device__ __forceinline__ void cluster_sync_all() {
    asm volatile("barrier.cluster.arrive.aligned;" ::: "memory");
    asm volatile("barrier.cluster.wait.aligned;" ::: "memory");
}

__global__ void __launch_bounds__(THREADS, 1) __cluster_dims__(CSZ, 1, 1)
sinkhorn_kernel(const float* __restrict__ A, float* __restrict__ Out)
{
    __shared__ __align__(16) float d_vec[N];
    __shared__ __align__(16) float ws[NWARP][N];     // col-partial workspace, 32KB
    __shared__ __align__(16) float xbuf[2][CSZ][N];  // peer col-partials, 8KB
    __shared__ __align__(8) unsigned long long mbar[2];
    __shared__ float red_sh[NWARP];
    __shared__ float mbuf[CSZ];

    const int tid  = threadIdx.x;
    const int w    = tid >> 5;
    const int l    = tid & 31;
    const int rank = blockIdx.x & (CSZ - 1);
    const int b    = blockIdx.x >> 2;

    const float* Am = A   + (size_t)b * N * N;
    float*       Om = Out + (size_t)b * N * N;

    if (tid == 0) {
        // count = CSZ-1 remote arrives complete a phase
        asm volatile("mbarrier.init.shared.b64 [%0], %1;"
                     :: "r"(smem_u32(&mbar[0])), "r"(CSZ - 1) : "memory");
        asm volatile("mbarrier.init.shared.b64 [%0], %1;"
                     :: "r"(smem_u32(&mbar[1])), "r"(CSZ - 1) : "memory");
        asm volatile("fence.mbarrier_init.release.cluster;" ::: "memory");
    }

    // ---- row layout: warp w owns local rows {2w, 2w+1}; lane l cols [8l,8l+8)
    const int r0   = 2 * w;
    const int c0   = l * 8;
    const int grow = rank * ROWS + r0;

    float er[16];  // [row r0: 8 cols][row r0+1: 8 cols]
    {
        float4 a0 = *(const float4*)(Am + grow * N + c0);
        float4 a1 = *(const float4*)(Am + grow * N + c0 + 4);
        float4 b0 = *(const float4*)(Am + (grow + 1) * N + c0);
        float4 b1 = *(const float4*)(Am + (grow + 1) * N + c0 + 4);
        er[0]=a0.x; er[1]=a0.y; er[2]=a0.z;  er[3]=a0.w;
        er[4]=a1.x; er[5]=a1.y; er[6]=a1.z;  er[7]=a1.w;
        er[8]=b0.x; er[9]=b0.y; er[10]=b0.z; er[11]=b0.w;
        er[12]=b1.x; er[13]=b1.y; er[14]=b1.z; er[15]=b1.w;
        #pragma unroll
        for (int k = 0; k < 16; k++) er[k] *= INV_TAU;
    }

    // ---- global per-matrix max m (for stable E = exp(a/tau - m))
    float mx = er[0];
    #pragma unroll
    for (int k = 1; k < 16; k++) mx = fmaxf(mx, er[k]);
    #pragma unroll
    for (int off = 16; off; off >>= 1)
        mx = fmaxf(mx, __shfl_xor_sync(0xffffffffu, mx, off));
    if (l == 0) red_sh[w] = mx;
    __syncthreads();
    if (w == 0) {
        float v = red_sh[l];
        #pragma unroll
        for (int off = 16; off; off >>= 1)
            v = fmaxf(v, __shfl_xor_sync(0xffffffffu, v, off));
        if (l == 0) {
            uint32_t slot = smem_u32(&mbuf[rank]);
            #pragma unroll
            for (int r = 0; r < CSZ; r++) st_cluster_f32(slot, r, v);
        }
    }
    cluster_sync_all();   // orders mbuf stores AND mbarrier inits cluster-wide
    float m = mbuf[0];
    #pragma unroll
    for (int r = 1; r < CSZ; r++) m = fmaxf(m, mbuf[r]);

    #pragma unroll
    for (int k = 0; k < 16; k++) er[k] = __expf(er[k] - m);

    if (tid < N) d_vec[tid] = 1.0f;   // c = 0 initially
    __syncthreads();

    // ---- hoisted remote addresses
    const uint32_t mb_local = smem_u32(&mbar[0]);
    // scatter targets: thread tid<N pushes its col partial to 3 peers
    uint32_t rsx[CSZ - 1];
    if (tid < N) {
        uint32_t laddr = smem_u32(&xbuf[0][rank][tid]);
        #pragma unroll
        for (int i = 0; i < CSZ - 1; i++)
            rsx[i] = mapa_rank(laddr, (uint32_t)((rank + 1 + i) & (CSZ - 1)));
    }
    // arrive targets: warp 0 lanes 0..2, one peer each
    uint32_t rmb = 0;
    if (w == 0 && l < CSZ - 1)
        rmb = mapa_rank(mb_local, (uint32_t)((rank + 1 + l) & (CSZ - 1)));
    const int p0 = (rank + 1) & (CSZ - 1);
    const int p1 = (rank + 2) & (CSZ - 1);
    const int p2 = (rank + 3) & (CSZ - 1);

    float rs0 = 1.0f, rs1 = 1.0f;   // 1/rowsum for my two rows (persist for epilogue)

    #pragma unroll 1
    for (int it = 0; it < NITER; it++) {
        const uint32_t par = (uint32_t)(it & 1);
        const uint32_t ph  = (uint32_t)((it >> 1) & 1);

        // ======== row pass (2 rows/warp) ========
        float4 d0 = *(const float4*)&d_vec[c0];
        float4 d1 = *(const float4*)&d_vec[c0 + 4];
        float s0 = er[0]*d0.x + er[1]*d0.y + er[2]*d0.z + er[3]*d0.w
                 + er[4]*d1.x + er[5]*d1.y + er[6]*d1.z + er[7]*d1.w;
        float s1 = er[8]*d0.x + er[9]*d0.y + er[10]*d0.z + er[11]*d0.w
                 + er[12]*d1.x + er[13]*d1.y + er[14]*d1.z + er[15]*d1.w;
        #pragma unroll
        for (int off = 16; off; off >>= 1) {
            s0 += __shfl_xor_sync(0xffffffffu, s0, off);
            s1 += __shfl_xor_sync(0xffffffffu, s1, off);
        }
        rs0 = __fdividef(1.0f, fmaxf(s0, 1e-30f));
        rs1 = __fdividef(1.0f, fmaxf(s1, 1e-30f));

        // ======== col partials straight from er (all lanes hold rs0,rs1) ====
        float4 q0, q1;
        q0.x = er[0]*rs0 + er[8]*rs1;   q0.y = er[1]*rs0 + er[9]*rs1;
        q0.z = er[2]*rs0 + er[10]*rs1;  q0.w = er[3]*rs0 + er[11]*rs1;
        q1.x = er[4]*rs0 + er[12]*rs1;  q1.y = er[5]*rs0 + er[13]*rs1;
        q1.z = er[6]*rs0 + er[14]*rs1;  q1.w = er[7]*rs0 + er[15]*rs1;
        *(float4*)&ws[w][c0]     = q0;
        *(float4*)&ws[w][c0 + 4] = q1;
        __syncthreads();

        // ======== local col sum + remote scatter ========
        float pown = 0.0f;
        if (tid < N) {
            float f0 = 0.f, f1 = 0.f, f2 = 0.f, f3 = 0.f;
            #pragma unroll
            for (int w2 = 0; w2 < NWARP; w2 += 4) {
                f0 += ws[w2][tid];
                f1 += ws[w2 + 1][tid];
                f2 += ws[w2 + 2][tid];
                f3 += ws[w2 + 3][tid];
            }
            pown = (f0 + f1) + (f2 + f3);
            uint32_t poff = par * (CSZ * N * 4u);
            #pragma unroll
            for (int i = 0; i < CSZ - 1; i++)
                st_cluster_f32_addr(rsx[i] + poff, pown);
        }
        __syncthreads();   // all scatter stores issued (CTA-visible)

        // publish: cumulative fence + one arrive per peer
        if (w == 0 && l < CSZ - 1) {
            fence_cluster();
            mbar_arrive_cluster(rmb + par * 8);
        }

        // ======== combine: own + 3 peer partials -> d[j] ========
        if (tid < N) {
            mbar_wait(mb_local + par * 8, ph);
            float f = pown + xbuf[par][p0][tid] + xbuf[par][p1][tid]
                           + xbuf[par][p2][tid];
            d_vec[tid] = __fdividef(1.0f, fmaxf(f, 1e-30f));
        }
        __syncthreads();
    }

    // ======== epilogue: P = E * e[i] * d[j] (2 rows/warp) ========
    {
        float4 d0 = *(const float4*)&d_vec[c0];
        float4 d1 = *(const float4*)&d_vec[c0 + 4];
        float4 o;
        o.x = er[0]*rs0*d0.x; o.y = er[1]*rs0*d0.y;
        o.z = er[2]*rs0*d0.z; o.w = er[3]*rs0*d0.w;
        *(float4*)(Om + grow * N + c0) = o;
        o.x = er[4]*rs0*d1.x; o.y = er[5]*rs0*d1.y;
        o.z = er[6]*rs0*d1.z; o.w = er[7]*rs0*d1.w;
        *(float4*)(Om + grow * N + c0 + 4) = o;
        o.x = er[8]*rs1*d0.x;  o.y = er[9]*rs1*d0.y;
        o.z = er[10]*rs1*d0.z; o.w = er[11]*rs1*d0.w;
        *(float4*)(Om + (grow + 1) * N + c0) = o;
        o.x = er[12]*rs1*d1.x; o.y = er[13]*rs1*d1.y;
        o.z = er[14]*rs1*d1.z; o.w = er[15]*rs1*d1.w;
        *(float4*)(Om + (grow + 1) * N + c0 + 4) = o;
    }

    // keep all CTAs alive until every in-flight remote store is consumed
    cluster_sync_all();
}

extern "C" void kernel_launch(void* const* d_in, const int* in_sizes, int n_in,
                              void* d_out, int out_size) {
    const float* alpha = (const float*)d_in[0];
    float* out = (float*)d_out;
    sinkhorn_kernel<<<NMAT * CSZ, THREADS>>>(alpha, out);
}